// round 2
// baseline (speedup 1.0000x reference)
#include <cuda_runtime.h>
#include <cuda_bf16.h>
#include <cstdint>

// Problem constants
#define BB   32      // batch
#define DD   4096    // model dim
#define HH   32      // q heads
#define HKV  8       // kv heads
#define GG   4       // q heads per kv head
#define DH   128     // head dim
#define TT   4096    // cache length
#define EQKV 6144    // 4096 + 1024 + 1024
#define CHUNK 64     // attention t-chunk per block
#define NCHUNK 64    // TT / CHUNK
#define SPLITS 32    // K-splits for projections
#define DSPL 128     // d per split (4096/32)

// ---------------- scratch (device globals; no runtime allocation) ----------------
__device__ float g_xq[BB * HH * DH];
__device__ float g_xk[BB * HKV * DH];
__device__ float g_v [BB * HKV * DH];
__device__ float g_q [BB * HH * DH];
__device__ float g_k [BB * HKV * DH];
__device__ float g_attn[BB * HH * DH];
__device__ float g_P1[SPLITS * BB * EQKV];             // qkv partials
__device__ float g_P2[SPLITS * BB * DD];               // wo partials
__device__ float g_pacc[BB * HKV * NCHUNK * GG * DH];  // flash partial acc
__device__ float g_pml [BB * HKV * NCHUNK * GG * 2];   // flash partial (m,l)

// ---------------- packed fp32x2 helpers (FFMA2 path, sm_100+) ----------------
__device__ __forceinline__ unsigned long long pk2(float lo, float hi) {
    unsigned long long r;
    asm("mov.b64 %0, {%1,%2};" : "=l"(r) : "f"(lo), "f"(hi));
    return r;
}
__device__ __forceinline__ void upk2(unsigned long long v, float& lo, float& hi) {
    asm("mov.b64 {%0,%1}, %2;" : "=f"(lo), "=f"(hi) : "l"(v));
}
__device__ __forceinline__ void fma2(unsigned long long& d, unsigned long long a, unsigned long long b) {
    asm("fma.rn.f32x2 %0, %1, %2, %0;" : "+l"(d) : "l"(a), "l"(b));
}

// ---------------- projection GEMV body ----------------
// out[b][e] = sum_d x[b][d] * w[d][e], M=32 rows, split over d.
// Block: 128 threads; thread owns 4 consecutive columns (LDG.128 weight loads)
// and all 16 batch pairs (FFMA2). Partial stores coalesced STG.128.
__device__ __forceinline__ void proj_body(
    const float* __restrict__ x, const float* __restrict__ w,
    int Ew, int le0, int gcol0, int d0,
    float* __restrict__ part, int partE)
{
    __shared__ float xs[DSPL * BB];   // 16 KB, [d_local][b]
    const int tid = threadIdx.x;

    #pragma unroll
    for (int k = 0; k < 32; k++) {
        int idx = tid + k * 128;
        int dl = idx >> 5, bb = idx & 31;
        xs[dl * 32 + bb] = x[bb * DD + d0 + dl];
    }
    __syncthreads();

    const unsigned long long* xs2 = (const unsigned long long*)xs; // [d_local][16 pairs]

    unsigned long long acc[16][4];
    #pragma unroll
    for (int jp = 0; jp < 16; jp++)
        #pragma unroll
        for (int c = 0; c < 4; c++) acc[jp][c] = 0ull;

    const float* wp = w + (size_t)d0 * Ew + le0 + tid * 4;

    #pragma unroll 4
    for (int dl = 0; dl < DSPL; dl++) {
        float4 w4 = *(const float4*)wp;
        unsigned long long wA = pk2(w4.x, w4.x);
        unsigned long long wB = pk2(w4.y, w4.y);
        unsigned long long wC = pk2(w4.z, w4.z);
        unsigned long long wD = pk2(w4.w, w4.w);
        const unsigned long long* xr = xs2 + dl * 16;
        #pragma unroll
        for (int jp = 0; jp < 16; jp++) {
            unsigned long long xv = xr[jp];
            fma2(acc[jp][0], wA, xv);
            fma2(acc[jp][1], wB, xv);
            fma2(acc[jp][2], wC, xv);
            fma2(acc[jp][3], wD, xv);
        }
        wp += Ew;
    }

    const int split = blockIdx.y;
    float* pb = part + (size_t)split * BB * partE + gcol0 + tid * 4;
    #pragma unroll
    for (int jp = 0; jp < 16; jp++) {
        float lo0, hi0, lo1, hi1, lo2, hi2, lo3, hi3;
        upk2(acc[jp][0], lo0, hi0);
        upk2(acc[jp][1], lo1, hi1);
        upk2(acc[jp][2], lo2, hi2);
        upk2(acc[jp][3], lo3, hi3);
        *(float4*)(pb + (size_t)(2 * jp) * partE)     = make_float4(lo0, lo1, lo2, lo3);
        *(float4*)(pb + (size_t)(2 * jp + 1) * partE) = make_float4(hi0, hi1, hi2, hi3);
    }
}

__global__ void __launch_bounds__(128)
proj_qkv_kernel(const float* __restrict__ x, const float* __restrict__ wq,
                const float* __restrict__ wk, const float* __restrict__ wv)
{
    int e0 = blockIdx.x * 512;
    const float* w; int Ew, le0;
    if (e0 < 4096)      { w = wq; Ew = 4096; le0 = e0; }
    else if (e0 < 5120) { w = wk; Ew = 1024; le0 = e0 - 4096; }
    else                { w = wv; Ew = 1024; le0 = e0 - 5120; }
    proj_body(x, w, Ew, le0, e0, blockIdx.y * DSPL, g_P1, EQKV);
}

__global__ void __launch_bounds__(128)
proj_o_kernel(const float* __restrict__ wo)
{
    int e0 = blockIdx.x * 512;
    proj_body(g_attn, wo, DD, e0, e0, blockIdx.y * DSPL, g_P2, DD);
}

// ---------------- reductions over K-splits ----------------
__global__ void reduce_qkv_kernel()
{
    int idx = blockIdx.x * 256 + threadIdx.x;
    if (idx >= BB * EQKV) return;
    int b = idx / EQKV, col = idx % EQKV;
    float s = 0.f;
    #pragma unroll 8
    for (int sp = 0; sp < SPLITS; sp++)
        s += g_P1[((size_t)sp * BB + b) * EQKV + col];
    if (col < 4096)      g_xq[b * 4096 + col] = s;
    else if (col < 5120) g_xk[b * 1024 + (col - 4096)] = s;
    else                 g_v [b * 1024 + (col - 5120)] = s;
}

__global__ void reduce_o_kernel(float* __restrict__ out)
{
    int idx = blockIdx.x * 256 + threadIdx.x;
    if (idx >= BB * DD) return;
    int b = idx >> 12, col = idx & 4095;
    float s = 0.f;
    #pragma unroll 8
    for (int sp = 0; sp < SPLITS; sp++)
        s += g_P2[((size_t)sp * BB + b) * DD + col];
    out[b * DD + col] = s;
}

// ---------------- RoPE: q[b,h,e] = sum_d xq[b,h,d] * rot[b,d,e] ----------------
__global__ void rotate_kernel(const float* __restrict__ rot, int rot_b_stride)
{
    int hh = blockIdx.x, b = blockIdx.y, tid = threadIdx.x;
    __shared__ float xs[DH];
    const float* src; float* dst;
    if (hh < HH) { src = g_xq + (b * HH + hh) * DH; dst = g_q + (b * HH + hh) * DH; }
    else         { src = g_xk + (b * HKV + (hh - HH)) * DH; dst = g_k + (b * HKV + (hh - HH)) * DH; }
    xs[tid] = src[tid];
    __syncthreads();
    const float* R = rot + (size_t)b * rot_b_stride;
    float a = 0.f;
    #pragma unroll 8
    for (int d = 0; d < DH; d++) a += xs[d] * R[d * DH + tid];
    dst[tid] = a;
}

// ---------------- flash decode, split-KV, cp.async pipelined ----------------
// grid (NCHUNK, HKV, B), block 256. CHUNK=64 tokens per block.
// SMEM (floats):
//   k_s   [0      .. 8192)   64x128, XOR-swizzled float4 rows
//   v_s   [8192   .. 16384)
//   q_s   [16384  .. 16896)  4 heads x 128 (pre-scaled)
//   p_s   [16896  .. 17152)  64 x float4 (scores -> probs)
//   s_wm  [17152  .. 17184)  per-warp max[8][4]
//   s_l   [17184  .. 17216)  per-warp l  [8][4]
//   s_out [17216  .. 18240)  [half][g][d]
#define ATTN_SMEM_FLOATS 18240

__global__ void __launch_bounds__(256)
attn_kernel(const float* __restrict__ kc, const float* __restrict__ vc,
            const int* __restrict__ sp_ptr)
{
    extern __shared__ float smem[];
    const int chunk = blockIdx.x, kvh = blockIdx.y, b = blockIdx.z;
    const int sp = *sp_ptr;
    const int t0 = chunk * CHUNK;
    if (t0 > sp) return;

    const int tid = threadIdx.x;
    const int bkv = b * HKV + kvh;

    float*  k_s  = smem;
    float*  v_s  = smem + 8192;
    float*  q_s  = smem + 16384;
    float4* p_s  = (float4*)(smem + 16896);
    float*  s_wm = smem + 17152;
    float*  s_l  = smem + 17184;
    float*  s_out = smem + 17216;

    const float* kbase = kc + (size_t)bkv * TT * DH;
    const float* vbase = vc + (size_t)bkv * TT * DH;

    // ---- issue K tile cp.async (group 0) ----
    #pragma unroll
    for (int it = 0; it < 8; it++) {
        int f = it * 256 + tid;
        int j = f >> 5, c = f & 31;
        int t = t0 + j;
        const float* src = (t == sp) ? (g_k + (size_t)bkv * DH + c * 4)
                                     : (kbase + (size_t)t * DH + c * 4);
        uint32_t dst = (uint32_t)__cvta_generic_to_shared(k_s + j * 128 + ((c ^ (j & 7)) << 2));
        asm volatile("cp.async.cg.shared.global [%0], [%1], 16;" :: "r"(dst), "l"(src));
    }
    asm volatile("cp.async.commit_group;");

    // ---- issue V tile cp.async (group 1) ----
    #pragma unroll
    for (int it = 0; it < 8; it++) {
        int f = it * 256 + tid;
        int j = f >> 5, c = f & 31;
        int t = t0 + j;
        const float* src = (t == sp) ? (g_v + (size_t)bkv * DH + c * 4)
                                     : (vbase + (size_t)t * DH + c * 4);
        uint32_t dst = (uint32_t)__cvta_generic_to_shared(v_s + j * 128 + ((c ^ (j & 7)) << 2));
        asm volatile("cp.async.cg.shared.global [%0], [%1], 16;" :: "r"(dst), "l"(src));
    }
    asm volatile("cp.async.commit_group;");

    // ---- stage q (scaled) while tiles stream ----
    if (tid < 128) {
        int g = tid >> 5, w = tid & 31;
        const float sc = 0.08838834764831845f;   // 1/sqrt(128)
        float4 qv = *(const float4*)(g_q + (size_t)(b * HH + kvh * GG + g) * DH + w * 4);
        ((float4*)q_s)[g * 32 + w] = make_float4(qv.x * sc, qv.y * sc, qv.z * sc, qv.w * sc);
    }

    asm volatile("cp.async.wait_group 1;");   // K tile complete
    __syncthreads();

    // ---- score phase: thread = (token j, dim-quarter q) ----
    const int j = tid >> 2, q = tid & 3;
    const int tj = t0 + j;
    float a0 = 0.f, a1 = 0.f, a2 = 0.f, a3 = 0.f;
    {
        const float4* krow = (const float4*)(k_s + j * 128);
        const float4* qp = (const float4*)q_s;
        #pragma unroll
        for (int d4 = 0; d4 < 8; d4++) {
            float4 kv = krow[(q * 8 + d4) ^ (j & 7)];
            float4 q0 = qp[0 * 32 + q * 8 + d4];
            float4 q1 = qp[1 * 32 + q * 8 + d4];
            float4 q2 = qp[2 * 32 + q * 8 + d4];
            float4 q3 = qp[3 * 32 + q * 8 + d4];
            a0 += q0.x * kv.x + q0.y * kv.y + q0.z * kv.z + q0.w * kv.w;
            a1 += q1.x * kv.x + q1.y * kv.y + q1.z * kv.z + q1.w * kv.w;
            a2 += q2.x * kv.x + q2.y * kv.y + q2.z * kv.z + q2.w * kv.w;
            a3 += q3.x * kv.x + q3.y * kv.y + q3.z * kv.z + q3.w * kv.w;
        }
    }
    // combine quarters (lanes xor1, xor2)
    a0 += __shfl_xor_sync(0xffffffffu, a0, 1);  a0 += __shfl_xor_sync(0xffffffffu, a0, 2);
    a1 += __shfl_xor_sync(0xffffffffu, a1, 1);  a1 += __shfl_xor_sync(0xffffffffu, a1, 2);
    a2 += __shfl_xor_sync(0xffffffffu, a2, 1);  a2 += __shfl_xor_sync(0xffffffffu, a2, 2);
    a3 += __shfl_xor_sync(0xffffffffu, a3, 1);  a3 += __shfl_xor_sync(0xffffffffu, a3, 2);
    if (tj > sp) { a0 = a1 = a2 = a3 = -1e30f; }
    if (q == 0) p_s[j] = make_float4(a0, a1, a2, a3);
    // warp max over 8 tokens (lanes xor 4,8,16)
    #pragma unroll
    for (int off = 4; off <= 16; off <<= 1) {
        a0 = fmaxf(a0, __shfl_xor_sync(0xffffffffu, a0, off));
        a1 = fmaxf(a1, __shfl_xor_sync(0xffffffffu, a1, off));
        a2 = fmaxf(a2, __shfl_xor_sync(0xffffffffu, a2, off));
        a3 = fmaxf(a3, __shfl_xor_sync(0xffffffffu, a3, off));
    }
    const int wid = tid >> 5, lane = tid & 31;
    if (lane == 0) {
        s_wm[wid * 4 + 0] = a0; s_wm[wid * 4 + 1] = a1;
        s_wm[wid * 4 + 2] = a2; s_wm[wid * 4 + 3] = a3;
    }
    __syncthreads();

    // ---- softmax: thread = (token j, head g=q) ----
    {
        const int g = q;
        float m = s_wm[g];
        #pragma unroll
        for (int w = 1; w < 8; w++) m = fmaxf(m, s_wm[w * 4 + g]);
        float sc = ((float*)p_s)[j * 4 + g];
        float p = (tj <= sp) ? __expf(sc - m) : 0.f;
        ((float*)p_s)[j * 4 + g] = p;
        float lsum = p;
        lsum += __shfl_xor_sync(0xffffffffu, lsum, 4);
        lsum += __shfl_xor_sync(0xffffffffu, lsum, 8);
        lsum += __shfl_xor_sync(0xffffffffu, lsum, 16);
        if (lane < 4) s_l[wid * 4 + lane] = lsum;
    }
    __syncthreads();

    if (tid < 4) {
        const int g = tid;
        float m = s_wm[g], L = 0.f;
        #pragma unroll
        for (int w = 0; w < 8; w++) { m = fmaxf(m, s_wm[w * 4 + g]); L += s_l[w * 4 + g]; }
        size_t mlb = (((size_t)bkv * NCHUNK + chunk) * GG + g) * 2;
        g_pml[mlb] = m;
        g_pml[mlb + 1] = L;
    }

    asm volatile("cp.async.wait_group 0;");   // V tile complete
    __syncthreads();

    // ---- value phase: thread = (dim d, token-half) ----
    {
        const int d = tid & 127, half = tid >> 7;
        float c0 = 0.f, c1 = 0.f, c2 = 0.f, c3 = 0.f;
        const int jb = half * 32;
        #pragma unroll 4
        for (int jj = 0; jj < 32; jj++) {
            int jr = jb + jj;
            float4 p4 = p_s[jr];
            float v = v_s[jr * 128 + ((((d >> 2) ^ (jr & 7)) << 2) | (d & 3))];
            c0 += p4.x * v; c1 += p4.y * v; c2 += p4.z * v; c3 += p4.w * v;
        }
        s_out[(half * 4 + 0) * 128 + d] = c0;
        s_out[(half * 4 + 1) * 128 + d] = c1;
        s_out[(half * 4 + 2) * 128 + d] = c2;
        s_out[(half * 4 + 3) * 128 + d] = c3;
    }
    __syncthreads();

    for (int r = tid; r < GG * DH; r += 256) {
        int g = r >> 7, dd = r & 127;
        float s = s_out[g * 128 + dd] + s_out[(4 + g) * 128 + dd];
        g_pacc[(((size_t)bkv * NCHUNK + chunk) * GG + g) * DH + dd] = s;
    }
}

// ---------------- combine split-KV partials ----------------
__global__ void combine_kernel(const int* __restrict__ sp_ptr)
{
    const int h = blockIdx.x, b = blockIdx.y, d = threadIdx.x;
    const int sp = *sp_ptr;
    const int nact = sp / CHUNK + 1;
    const int kvh = h >> 2, g = h & 3;
    const int bkv = b * HKV + kvh;

    float M = -1e30f;
    for (int c = 0; c < nact; c++)
        M = fmaxf(M, g_pml[(((size_t)bkv * NCHUNK + c) * GG + g) * 2]);

    float L = 0.f, acc = 0.f;
    for (int c = 0; c < nact; c++) {
        size_t mlb = (((size_t)bkv * NCHUNK + c) * GG + g) * 2;
        float f = __expf(g_pml[mlb] - M);
        L += g_pml[mlb + 1] * f;
        acc += g_pacc[(((size_t)bkv * NCHUNK + c) * GG + g) * DH + d] * f;
    }
    g_attn[(size_t)(b * HH + h) * DH + d] = acc / L;
}

// ---------------- launcher ----------------
extern "C" void kernel_launch(void* const* d_in, const int* in_sizes, int n_in,
                              void* d_out, int out_size)
{
    const float* x   = (const float*)d_in[0];
    const float* wq  = (const float*)d_in[1];
    const float* wk  = (const float*)d_in[2];
    const float* wv  = (const float*)d_in[3];
    const float* wo  = (const float*)d_in[4];
    const float* rot = (const float*)d_in[5];
    // d_in[6] = attn_mask: not read (semantics derived from start_pos)
    const float* kc  = (const float*)d_in[7];
    const float* vc  = (const float*)d_in[8];
    const int*   sp  = (const int*)d_in[9];
    float* out = (float*)d_out;

    int rot_b_stride = (in_sizes[5] >= BB * DH * DH) ? DH * DH : 0;

    cudaFuncSetAttribute(attn_kernel, cudaFuncAttributeMaxDynamicSharedMemorySize,
                         ATTN_SMEM_FLOATS * 4);

    proj_qkv_kernel<<<dim3(EQKV / 512, SPLITS), 128>>>(x, wq, wk, wv);
    reduce_qkv_kernel<<<(BB * EQKV + 255) / 256, 256>>>();
    rotate_kernel<<<dim3(HH + HKV, BB), DH>>>(rot, rot_b_stride);
    attn_kernel<<<dim3(NCHUNK, HKV, BB), 256, ATTN_SMEM_FLOATS * 4>>>(kc, vc, sp);
    combine_kernel<<<dim3(HH, BB), DH>>>(sp);
    proj_o_kernel<<<dim3(DD / 512, SPLITS), 128>>>(wo);
    reduce_o_kernel<<<(BB * DD + 255) / 256, 256>>>(out);
}

// round 3
// speedup vs baseline: 1.2408x; 1.2408x over previous
#include <cuda_runtime.h>
#include <cuda_bf16.h>
#include <cstdint>

// Problem constants
#define BB   32      // batch
#define DD   4096    // model dim
#define HH   32      // q heads
#define HKV  8       // kv heads
#define GG   4       // q heads per kv head
#define DH   128     // head dim
#define TT   4096    // cache length
#define EQKV 6144    // 4096 + 1024 + 1024
#define SPLITS 32    // K-splits for projections
#define DSPL 128     // d per split (4096/32)

// attention split config
#define NSPLIT 8     // token splits per (b,kvh)
#define TSPLIT 512   // TT / NSPLIT
#define CH     32    // tokens per chunk
#define NCHS   16    // chunks per split

// ---------------- scratch (device globals; no runtime allocation) ----------------
__device__ float g_xq[BB * HH * DH];
__device__ float g_xk[BB * HKV * DH];
__device__ float g_v [BB * HKV * DH];
__device__ float g_q [BB * HH * DH];
__device__ float g_k [BB * HKV * DH];
__device__ float g_attn[BB * HH * DH];
__device__ float g_P1[SPLITS * BB * EQKV];               // qkv partials
__device__ float g_P2[SPLITS * BB * DD];                 // wo partials
__device__ float g_pacc[BB * HKV * NSPLIT * GG * DH];    // flash partial acc
__device__ float g_pml [BB * HKV * NSPLIT * GG * 2];     // flash partial (m,l)

// ---------------- packed fp32x2 helpers (FFMA2 path, sm_100+) ----------------
__device__ __forceinline__ unsigned long long pk2(float lo, float hi) {
    unsigned long long r;
    asm("mov.b64 %0, {%1,%2};" : "=l"(r) : "f"(lo), "f"(hi));
    return r;
}
__device__ __forceinline__ void upk2(unsigned long long v, float& lo, float& hi) {
    asm("mov.b64 {%0,%1}, %2;" : "=f"(lo), "=f"(hi) : "l"(v));
}
__device__ __forceinline__ void fma2(unsigned long long& d, unsigned long long a, unsigned long long b) {
    asm("fma.rn.f32x2 %0, %1, %2, %0;" : "+l"(d) : "l"(a), "l"(b));
}

// ---------------- projection GEMV body ----------------
// out[b][e] = sum_d x[b][d] * w[d][e], M=32 rows, split over d.
// 256 threads; thread owns 2 consecutive columns (LDG.64 weight loads)
// and all 16 batch pairs (FFMA2). acc = 64 regs.
__device__ __forceinline__ void proj_body(
    const float* __restrict__ x, const float* __restrict__ w,
    int Ew, int le0, int gcol0, int d0,
    float* __restrict__ part, int partE)
{
    __shared__ float xs[DSPL * BB];   // 16 KB, [d_local][b]
    const int tid = threadIdx.x;

    #pragma unroll
    for (int k = 0; k < 16; k++) {
        int idx = tid + k * 256;
        int dl = idx >> 5, bb = idx & 31;
        xs[dl * 32 + bb] = x[bb * DD + d0 + dl];
    }
    __syncthreads();

    const unsigned long long* xs2 = (const unsigned long long*)xs; // [d_local][16 pairs]

    unsigned long long acc[16][2];
    #pragma unroll
    for (int jp = 0; jp < 16; jp++) { acc[jp][0] = 0ull; acc[jp][1] = 0ull; }

    const float* wp = w + (size_t)d0 * Ew + le0 + tid * 2;

    #pragma unroll 2
    for (int dl = 0; dl < DSPL; dl++) {
        float2 w2 = *(const float2*)wp;
        unsigned long long uA = pk2(w2.x, w2.x);
        unsigned long long uB = pk2(w2.y, w2.y);
        const unsigned long long* xr = xs2 + dl * 16;
        #pragma unroll
        for (int jp = 0; jp < 16; jp++) {
            unsigned long long xv = xr[jp];
            fma2(acc[jp][0], uA, xv);
            fma2(acc[jp][1], uB, xv);
        }
        wp += Ew;
    }

    const int split = blockIdx.y;
    float* pb = part + (size_t)split * BB * partE + gcol0 + tid * 2;
    #pragma unroll
    for (int jp = 0; jp < 16; jp++) {
        float lo0, hi0, lo1, hi1;
        upk2(acc[jp][0], lo0, hi0);
        upk2(acc[jp][1], lo1, hi1);
        *(float2*)(pb + (size_t)(2 * jp) * partE)     = make_float2(lo0, lo1);
        *(float2*)(pb + (size_t)(2 * jp + 1) * partE) = make_float2(hi0, hi1);
    }
}

__global__ void __launch_bounds__(256)
proj_qkv_kernel(const float* __restrict__ x, const float* __restrict__ wq,
                const float* __restrict__ wk, const float* __restrict__ wv)
{
    int e0 = blockIdx.x * 512;
    const float* w; int Ew, le0;
    if (e0 < 4096)      { w = wq; Ew = 4096; le0 = e0; }
    else if (e0 < 5120) { w = wk; Ew = 1024; le0 = e0 - 4096; }
    else                { w = wv; Ew = 1024; le0 = e0 - 5120; }
    proj_body(x, w, Ew, le0, e0, blockIdx.y * DSPL, g_P1, EQKV);
}

__global__ void __launch_bounds__(256)
proj_o_kernel(const float* __restrict__ wo)
{
    int e0 = blockIdx.x * 512;
    proj_body(g_attn, wo, DD, e0, e0, blockIdx.y * DSPL, g_P2, DD);
}

// ---------------- reductions over K-splits ----------------
__global__ void reduce_qkv_kernel()
{
    int idx = blockIdx.x * 256 + threadIdx.x;
    if (idx >= BB * EQKV) return;
    int b = idx / EQKV, col = idx % EQKV;
    float s = 0.f;
    #pragma unroll 8
    for (int sp = 0; sp < SPLITS; sp++)
        s += g_P1[((size_t)sp * BB + b) * EQKV + col];
    if (col < 4096)      g_xq[b * 4096 + col] = s;
    else if (col < 5120) g_xk[b * 1024 + (col - 4096)] = s;
    else                 g_v [b * 1024 + (col - 5120)] = s;
}

__global__ void reduce_o_kernel(float* __restrict__ out)
{
    int idx = blockIdx.x * 256 + threadIdx.x;
    if (idx >= BB * DD) return;
    int b = idx >> 12, col = idx & 4095;
    float s = 0.f;
    #pragma unroll 8
    for (int sp = 0; sp < SPLITS; sp++)
        s += g_P2[((size_t)sp * BB + b) * DD + col];
    out[b * DD + col] = s;
}

// ---------------- RoPE: q[b,h,e] = sum_d xq[b,h,d] * rot[b,d,e] ----------------
__global__ void rotate_kernel(const float* __restrict__ rot, int rot_b_stride)
{
    int hh = blockIdx.x, b = blockIdx.y, tid = threadIdx.x;
    __shared__ float xs[DH];
    const float* src; float* dst;
    if (hh < HH) { src = g_xq + (b * HH + hh) * DH; dst = g_q + (b * HH + hh) * DH; }
    else         { src = g_xk + (b * HKV + (hh - HH)) * DH; dst = g_k + (b * HKV + (hh - HH)) * DH; }
    xs[tid] = src[tid];
    __syncthreads();
    const float* R = rot + (size_t)b * rot_b_stride;
    float a = 0.f;
    #pragma unroll 8
    for (int d = 0; d < DH; d++) a += xs[d] * R[d * DH + tid];
    dst[tid] = a;
}

// ---------------- flash decode: persistent split CTA, double-buffered cp.async ----------------
// grid (NSPLIT, HKV, B), block 256. Each CTA handles 512 tokens = 16 chunks of 32.
// SMEM floats: kb[2][32*128], vb[2][32*128], q_s[512], p_sc[128], s_wm[16], s_l[16],
//              mrun[4], lrun[4], fs[4], M[4], s_out[512]
#define SM_K0   0
#define SM_K1   4096
#define SM_V0   8192
#define SM_V1   12288
#define SM_QS   16384
#define SM_PSC  16896
#define SM_WM   17024
#define SM_SL   17040
#define SM_MRUN 17056
#define SM_LRUN 17060
#define SM_FS   17064
#define SM_MM   17068
#define SM_OUT  17072
#define ATTN_SMEM_FLOATS 17584

__device__ __forceinline__ void issue_chunk(
    float* kb, float* vb,
    const float* __restrict__ kbase, const float* __restrict__ vbase,
    const float* __restrict__ gk, const float* __restrict__ gv,
    int t0c, int sp, int tid)
{
    #pragma unroll
    for (int it = 0; it < 4; it++) {
        int f = it * 256 + tid;
        int j = f >> 5, c = f & 31;
        int t = t0c + j;
        const float* ksrc = (t == sp) ? (gk + c * 4) : (kbase + (size_t)t * DH + c * 4);
        uint32_t kd = (uint32_t)__cvta_generic_to_shared(kb + j * 128 + ((c ^ (j & 7)) << 2));
        asm volatile("cp.async.cg.shared.global [%0], [%1], 16;" :: "r"(kd), "l"(ksrc));
        const float* vsrc = (t == sp) ? (gv + c * 4) : (vbase + (size_t)t * DH + c * 4);
        uint32_t vd = (uint32_t)__cvta_generic_to_shared(vb + j * 128 + ((c ^ (j & 7)) << 2));
        asm volatile("cp.async.cg.shared.global [%0], [%1], 16;" :: "r"(vd), "l"(vsrc));
    }
    asm volatile("cp.async.commit_group;");
}

__global__ void __launch_bounds__(256)
attn_kernel(const float* __restrict__ kc, const float* __restrict__ vc,
            const int* __restrict__ sp_ptr)
{
    extern __shared__ float smem[];
    const int split = blockIdx.x, kvh = blockIdx.y, b = blockIdx.z;
    const int sp = *sp_ptr;
    const int t0s = split * TSPLIT;
    if (t0s > sp) return;
    const int active = min(TSPLIT, sp + 1 - t0s);
    const int nch = (active + CH - 1) / CH;

    const int tid = threadIdx.x;
    const int bkv = b * HKV + kvh;

    const float* kbase = kc + (size_t)bkv * TT * DH;
    const float* vbase = vc + (size_t)bkv * TT * DH;
    const float* gk = g_k + (size_t)bkv * DH;
    const float* gv = g_v + (size_t)bkv * DH;

    // ---- prologue: stage q (scaled, XOR-g swizzle), init softmax state ----
    if (tid < 128) {
        int g = tid >> 5, c = tid & 31;
        const float sc = 0.08838834764831845f;   // 1/sqrt(128)
        float4 qv = *(const float4*)(g_q + (size_t)(b * HH + kvh * GG + g) * DH + c * 4);
        ((float4*)(smem + SM_QS))[g * 32 + (c ^ g)] =
            make_float4(qv.x * sc, qv.y * sc, qv.z * sc, qv.w * sc);
    }
    if (tid < 4) { smem[SM_MRUN + tid] = -1e30f; smem[SM_LRUN + tid] = 0.f; }

    issue_chunk(smem + SM_K0, smem + SM_V0, kbase, vbase, gk, gv, t0s, sp, tid);
    if (nch > 1)
        issue_chunk(smem + SM_K1, smem + SM_V1, kbase, vbase, gk, gv, t0s + CH, sp, tid);

    // value-phase persistent accumulators: thread = (d, token-half)
    const int d = tid & 127, vhalf = tid >> 7;
    float acc0 = 0.f, acc1 = 0.f, acc2 = 0.f, acc3 = 0.f;

    // score-phase mapping: thread = (token j, head g, dim-half h)
    const int sj = tid >> 3, sg = (tid >> 1) & 3, sh = tid & 1;

    for (int ic = 0; ic < nch; ic++) {
        if (ic + 1 < nch) { asm volatile("cp.async.wait_group 1;"); }
        else              { asm volatile("cp.async.wait_group 0;"); }
        __syncthreads();

        float* kb = smem + ((ic & 1) ? SM_K1 : SM_K0);
        float* vb = smem + ((ic & 1) ? SM_V1 : SM_V0);

        // ---- scores: dot(q[g], k[j]) over 64 dims per thread, 1 shfl ----
        {
            const float4* kr = (const float4*)kb + sj * 32;
            const float4* qp = (const float4*)(smem + SM_QS) + sg * 32;
            float s = 0.f;
            #pragma unroll
            for (int d4 = 0; d4 < 16; d4++) {
                int c = sh * 16 + d4;
                float4 k4 = kr[c ^ (sj & 7)];
                float4 q4 = qp[c ^ sg];
                s += q4.x * k4.x + q4.y * k4.y + q4.z * k4.z + q4.w * k4.w;
            }
            s += __shfl_xor_sync(0xffffffffu, s, 1);
            int tj = t0s + ic * CH + sj;
            if (sh == 0) smem[SM_PSC + sj * 4 + sg] = (tj <= sp) ? s : -1e30f;
        }
        __syncthreads();

        // ---- block max per head ----
        if (tid < 128) {
            int g2 = tid & 3, j2 = tid >> 2;
            float sm = smem[SM_PSC + j2 * 4 + g2];
            sm = fmaxf(sm, __shfl_xor_sync(0xffffffffu, sm, 4));
            sm = fmaxf(sm, __shfl_xor_sync(0xffffffffu, sm, 8));
            sm = fmaxf(sm, __shfl_xor_sync(0xffffffffu, sm, 16));
            if ((tid & 31) < 4) smem[SM_WM + (tid >> 5) * 4 + g2] = sm;
        }
        __syncthreads();

        if (tid < 4) {
            float bm = fmaxf(fmaxf(smem[SM_WM + tid], smem[SM_WM + 4 + tid]),
                             fmaxf(smem[SM_WM + 8 + tid], smem[SM_WM + 12 + tid]));
            float mold = smem[SM_MRUN + tid];
            float M = fmaxf(mold, bm);
            smem[SM_FS + tid] = __expf(mold - M);
            smem[SM_MM + tid] = M;
            smem[SM_MRUN + tid] = M;
        }
        __syncthreads();

        // ---- exp + row sums ----
        if (tid < 128) {
            int g2 = tid & 3, j2 = tid >> 2;
            float sv = smem[SM_PSC + j2 * 4 + g2];
            float p = __expf(sv - smem[SM_MM + g2]);
            smem[SM_PSC + j2 * 4 + g2] = p;
            float l = p;
            l += __shfl_xor_sync(0xffffffffu, l, 4);
            l += __shfl_xor_sync(0xffffffffu, l, 8);
            l += __shfl_xor_sync(0xffffffffu, l, 16);
            if ((tid & 31) < 4) smem[SM_SL + (tid >> 5) * 4 + g2] = l;
        }
        __syncthreads();

        if (tid < 4) {
            smem[SM_LRUN + tid] = smem[SM_LRUN + tid] * smem[SM_FS + tid]
                + smem[SM_SL + tid] + smem[SM_SL + 4 + tid]
                + smem[SM_SL + 8 + tid] + smem[SM_SL + 12 + tid];
        }

        // ---- value phase: rescale + accumulate 16 tokens ----
        {
            float f0 = smem[SM_FS + 0], f1 = smem[SM_FS + 1];
            float f2 = smem[SM_FS + 2], f3 = smem[SM_FS + 3];
            acc0 *= f0; acc1 *= f1; acc2 *= f2; acc3 *= f3;
            #pragma unroll 4
            for (int jj = 0; jj < 16; jj++) {
                int jr = vhalf * 16 + jj;
                float4 p4 = *(const float4*)(smem + SM_PSC + jr * 4);
                float v = vb[jr * 128 + ((((d >> 2) ^ (jr & 7)) << 2) | (d & 3))];
                acc0 += p4.x * v; acc1 += p4.y * v; acc2 += p4.z * v; acc3 += p4.w * v;
            }
        }
        __syncthreads();

        if (ic + 2 < nch) {
            float* kb2 = smem + ((ic & 1) ? SM_K1 : SM_K0);
            float* vb2 = smem + ((ic & 1) ? SM_V1 : SM_V0);
            issue_chunk(kb2, vb2, kbase, vbase, gk, gv, t0s + (ic + 2) * CH, sp, tid);
        }
    }

    // ---- epilogue: merge halves, write partials ----
    if (vhalf == 0) {
        smem[SM_OUT + 0 * 128 + d] = acc0;
        smem[SM_OUT + 1 * 128 + d] = acc1;
        smem[SM_OUT + 2 * 128 + d] = acc2;
        smem[SM_OUT + 3 * 128 + d] = acc3;
    }
    __syncthreads();
    if (vhalf == 1) {
        smem[SM_OUT + 0 * 128 + d] += acc0;
        smem[SM_OUT + 1 * 128 + d] += acc1;
        smem[SM_OUT + 2 * 128 + d] += acc2;
        smem[SM_OUT + 3 * 128 + d] += acc3;
    }
    __syncthreads();

    size_t obase = (((size_t)bkv * NSPLIT + split) * GG) * DH;
    for (int r = tid; r < GG * DH; r += 256)
        g_pacc[obase + r] = smem[SM_OUT + r];
    if (tid < 4) {
        size_t mlb = (((size_t)bkv * NSPLIT + split) * GG + tid) * 2;
        g_pml[mlb] = smem[SM_MRUN + tid];
        g_pml[mlb + 1] = smem[SM_LRUN + tid];
    }
}

// ---------------- combine split-KV partials ----------------
__global__ void combine_kernel(const int* __restrict__ sp_ptr)
{
    const int h = blockIdx.x, b = blockIdx.y, d = threadIdx.x;
    const int sp = *sp_ptr;
    const int nact = sp / TSPLIT + 1;
    const int kvh = h >> 2, g = h & 3;
    const int bkv = b * HKV + kvh;

    float M = -1e30f;
    for (int c = 0; c < nact; c++)
        M = fmaxf(M, g_pml[(((size_t)bkv * NSPLIT + c) * GG + g) * 2]);

    float L = 0.f, acc = 0.f;
    for (int c = 0; c < nact; c++) {
        size_t mlb = (((size_t)bkv * NSPLIT + c) * GG + g) * 2;
        float f = __expf(g_pml[mlb] - M);
        L += g_pml[mlb + 1] * f;
        acc += g_pacc[(((size_t)bkv * NSPLIT + c) * GG + g) * DH + d] * f;
    }
    g_attn[(size_t)(b * HH + h) * DH + d] = acc / L;
}

// ---------------- launcher ----------------
extern "C" void kernel_launch(void* const* d_in, const int* in_sizes, int n_in,
                              void* d_out, int out_size)
{
    const float* x   = (const float*)d_in[0];
    const float* wq  = (const float*)d_in[1];
    const float* wk  = (const float*)d_in[2];
    const float* wv  = (const float*)d_in[3];
    const float* wo  = (const float*)d_in[4];
    const float* rot = (const float*)d_in[5];
    // d_in[6] = attn_mask: not read (semantics derived from start_pos)
    const float* kc  = (const float*)d_in[7];
    const float* vc  = (const float*)d_in[8];
    const int*   sp  = (const int*)d_in[9];
    float* out = (float*)d_out;

    int rot_b_stride = (in_sizes[5] >= BB * DH * DH) ? DH * DH : 0;

    cudaFuncSetAttribute(attn_kernel, cudaFuncAttributeMaxDynamicSharedMemorySize,
                         ATTN_SMEM_FLOATS * 4);

    proj_qkv_kernel<<<dim3(EQKV / 512, SPLITS), 256>>>(x, wq, wk, wv);
    reduce_qkv_kernel<<<(BB * EQKV + 255) / 256, 256>>>();
    rotate_kernel<<<dim3(HH + HKV, BB), DH>>>(rot, rot_b_stride);
    attn_kernel<<<dim3(NSPLIT, HKV, BB), 256, ATTN_SMEM_FLOATS * 4>>>(kc, vc, sp);
    combine_kernel<<<dim3(HH, BB), DH>>>(sp);
    proj_o_kernel<<<dim3(DD / 512, SPLITS), 256>>>(wo);
    reduce_o_kernel<<<(BB * DD + 255) / 256, 256>>>(out);
}